// round 7
// baseline (speedup 1.0000x reference)
#include <cuda_runtime.h>

#define CEPS 1e-3f

// scratch (allocation-free rule: __device__ globals)
__device__ float g_y0[100000 * 16];
__device__ float g_y1[100000 * 16];
__device__ float g_merged[200000 * 16];
__device__ float g_stats[64];   // [0:16) sum0, [16:32) sq0, [32:48) sum1, [48:64) sq1

// ---------------------------------------------------------------------------
// Submanifold 3x3x3 conv: y[n,o] = sum_k sum_c x[nbr[n,k],c] * W[k,c,o]
// Block: 256 threads -> 128 rows x 16 out-ch.  Thread: 2 rows x 4 couts.
// Per (k,c): LDS.64 x (conflict-free) + LDS.128 W (conflict-free) -> 8 FMA.
// Neighbor table staged to SMEM (coalesced). Gather tile + W slice are
// double-buffered: stage k+1 while computing k, one sync per k.
// LAYER==1 computes the layer-0 BN affine from g_stats in the prologue and
// applies BN+ReLU to gathered values on the fly (missing neighbors stay 0).
// ---------------------------------------------------------------------------
template <int LAYER>
__global__ __launch_bounds__(256) void conv_kernel(
    const float* __restrict__ x, const int* __restrict__ nbr,
    const float* __restrict__ W, float* __restrict__ y,
    const float* __restrict__ g, const float* __restrict__ b,
    int N, float invN)
{
    __shared__ int   snbr[128 * 27];      // 13.8 KB
    __shared__ float xs[2][16 * 132];     // 16.9 KB, transposed [c][row]
    __shared__ float wk[2][256];          //  2.0 KB, per-k [c][o]
    __shared__ float saff[32];
    __shared__ float sstat[32];

    int tid = threadIdx.x;
    int row0 = blockIdx.x * 128;

    // stage neighbor table, coalesced
    int lim = (N - row0) * 27;
    for (int i = tid; i < 128 * 27; i += 256)
        snbr[i] = (i < lim) ? nbr[row0 * 27 + i] : -1;

    if (tid < 32) sstat[tid] = 0.f;
    if (LAYER == 1 && tid < 16) {
        float mu  = g_stats[tid] * invN;
        float var = g_stats[16 + tid] * invN - mu * mu;
        float s   = g[tid] * rsqrtf(var + CEPS);
        saff[tid]      = s;
        saff[16 + tid] = b[tid] - mu * s;
    }

    int tx = tid & 3;     // cout quad: channels tx*4 .. tx*4+3
    int ty = tid >> 2;    // row pair:  rows ty*2, ty*2+1

    float acc0[4] = {0.f, 0.f, 0.f, 0.f};
    float acc1[4] = {0.f, 0.f, 0.f, 0.f};

    __syncthreads();

    auto stage = [&](int k, int buf) {
        wk[buf][tid] = W[k * 256 + tid];
#pragma unroll
        for (int i = 0; i < 2; i++) {
            int e  = tid + i * 256;     // 0..511 -> (row, c-quad)
            int r  = e >> 2;            // 0..127
            int c4 = (e & 3) * 4;
            int id = snbr[r * 27 + k];
            float4 v = make_float4(0.f, 0.f, 0.f, 0.f);
            if (id >= 0) {
                v = *(const float4*)(x + id * 16 + c4);
                if (LAYER == 1) {
                    v.x = fmaxf(fmaf(v.x, saff[c4 + 0], saff[16 + c4 + 0]), 0.f);
                    v.y = fmaxf(fmaf(v.y, saff[c4 + 1], saff[16 + c4 + 1]), 0.f);
                    v.z = fmaxf(fmaf(v.z, saff[c4 + 2], saff[16 + c4 + 2]), 0.f);
                    v.w = fmaxf(fmaf(v.w, saff[c4 + 3], saff[16 + c4 + 3]), 0.f);
                }
            }
            xs[buf][(c4 + 0) * 132 + r] = v.x;
            xs[buf][(c4 + 1) * 132 + r] = v.y;
            xs[buf][(c4 + 2) * 132 + r] = v.z;
            xs[buf][(c4 + 3) * 132 + r] = v.w;
        }
    };

    stage(0, 0);
    __syncthreads();

    for (int k = 0; k < 27; k++) {
        int cur = k & 1;
        if (k < 26) stage(k + 1, cur ^ 1);

        const float* xb = xs[cur] + ty * 2;
        const float* wb = wk[cur] + tx * 4;
#pragma unroll
        for (int c = 0; c < 16; c++) {
            float2 xv = *(const float2*)(xb + c * 132);   // rows ty*2, ty*2+1
            float4 wv = *(const float4*)(wb + c * 16);    // couts tx*4..+3
            acc0[0] = fmaf(xv.x, wv.x, acc0[0]);
            acc0[1] = fmaf(xv.x, wv.y, acc0[1]);
            acc0[2] = fmaf(xv.x, wv.z, acc0[2]);
            acc0[3] = fmaf(xv.x, wv.w, acc0[3]);
            acc1[0] = fmaf(xv.y, wv.x, acc1[0]);
            acc1[1] = fmaf(xv.y, wv.y, acc1[1]);
            acc1[2] = fmaf(xv.y, wv.z, acc1[2]);
            acc1[3] = fmaf(xv.y, wv.w, acc1[3]);
        }
        __syncthreads();
    }

    // ---- write y (rows for n >= N have all-zero acc; harmless to stats) ----
    int r0 = row0 + ty * 2;
    if (r0 < N)
        *(float4*)(y + r0 * 16 + tx * 4) = make_float4(acc0[0], acc0[1], acc0[2], acc0[3]);
    if (r0 + 1 < N)
        *(float4*)(y + (r0 + 1) * 16 + tx * 4) = make_float4(acc1[0], acc1[1], acc1[2], acc1[3]);

    // ---- BN statistics: zero rows contribute zero, no guard needed ----
    float s[4], q[4];
#pragma unroll
    for (int j = 0; j < 4; j++) {
        s[j] = acc0[j] + acc1[j];
        q[j] = acc0[j] * acc0[j] + acc1[j] * acc1[j];
    }
#pragma unroll
    for (int off = 4; off < 32; off <<= 1) {
#pragma unroll
        for (int j = 0; j < 4; j++) {
            s[j] += __shfl_xor_sync(0xffffffffu, s[j], off);
            q[j] += __shfl_xor_sync(0xffffffffu, q[j], off);
        }
    }
    if ((tid & 31) < 4) {   // lanes 0..3 hold totals for cout quad (lane)
#pragma unroll
        for (int j = 0; j < 4; j++) {
            atomicAdd(&sstat[tx * 4 + j], s[j]);
            atomicAdd(&sstat[16 + tx * 4 + j], q[j]);
        }
    }
    __syncthreads();
    if (tid < 32) atomicAdd(&g_stats[(LAYER == 0 ? 0 : 32) + tid], sstat[tid]);
}

// tiny stats-zero kernel (keeps launch indices deterministic for ncu)
__global__ void zero_stats_kernel() {
    if (threadIdx.x < 64) g_stats[threadIdx.x] = 0.f;
}

// t2 = f2 @ Wobo + bobo, atomicAdd-scatter into merged (runs before convs)
__global__ __launch_bounds__(256) void fuse_t2_kernel(
    const float* __restrict__ f2, const float* __restrict__ Wobo,
    const float* __restrict__ bobo, const int* __restrict__ seg2, int N)
{
    __shared__ float Wo[256];
    __shared__ float sf[16 * 17];
    __shared__ float sb[16];
    int tid = threadIdx.x;
    Wo[tid] = Wobo[tid];
    if (tid < 16) sb[tid] = bobo[tid];
    int n0 = blockIdx.x * 16;
    if (tid < 64) {
        int r = tid >> 2, c4 = (tid & 3) * 4;
        float4 v = make_float4(0.f, 0.f, 0.f, 0.f);
        if (n0 + r < N) v = *(const float4*)(f2 + (n0 + r) * 16 + c4);
        sf[r * 17 + c4 + 0] = v.x; sf[r * 17 + c4 + 1] = v.y;
        sf[r * 17 + c4 + 2] = v.z; sf[r * 17 + c4 + 3] = v.w;
    }
    __syncthreads();
    int tx = tid & 15, ty = tid >> 4;
    int n = n0 + ty;
    if (n >= N) return;
    float acc = sb[tx];
#pragma unroll
    for (int c = 0; c < 16; c++)
        acc = fmaf(sf[ty * 17 + c], Wo[c * 16 + tx], acc);
    atomicAdd(&g_merged[seg2[n] * 16 + tx], acc);
}

// h = relu(bn1(y1)), atomicAdd-scatter into merged
__global__ __launch_bounds__(256) void fuse_h_kernel(
    const float* __restrict__ y1, const float* __restrict__ g1,
    const float* __restrict__ b1, const int* __restrict__ seg, int N, float invN)
{
    __shared__ float saff[32];
    int tid = threadIdx.x;
    if (tid < 16) {
        float mu  = g_stats[32 + tid] * invN;
        float var = g_stats[48 + tid] * invN - mu * mu;
        float s   = g1[tid] * rsqrtf(var + CEPS);
        saff[tid]      = s;
        saff[16 + tid] = b1[tid] - mu * s;
    }
    __syncthreads();
    int tx = tid & 15, ty = tid >> 4;
    int n = blockIdx.x * 16 + ty;
    if (n >= N) return;
    float h = fmaxf(fmaf(y1[n * 16 + tx], saff[tx], saff[16 + tx]), 0.f);
    atomicAdd(&g_merged[seg[n] * 16 + tx], h);
}

// out[u,:] = merged[u,:] @ Wf + bf.
// Block: 256 threads -> 32 rows x 128 cols. Warp = 4 rows (row idx warp-
// uniform -> x reads are pure SMEM broadcast; W reads LDS.128 conflict-free).
__global__ __launch_bounds__(256) void out_kernel(
    const float* __restrict__ Wf, const float* __restrict__ bf,
    float* __restrict__ out, int U)
{
    __shared__ float Wfs[2048];
    __shared__ float sx[32 * 16];
    int tid = threadIdx.x;
    for (int i = tid; i < 2048; i += 256) Wfs[i] = Wf[i];
    int u0 = blockIdx.x * 32;
    if (tid < 128) {
        int r = tid >> 2, c4 = (tid & 3) * 4;
        float4 v = make_float4(0.f, 0.f, 0.f, 0.f);
        if (u0 + r < U) v = *(const float4*)(g_merged + (u0 + r) * 16 + c4);
        *(float4*)(sx + r * 16 + c4) = v;
    }
    __syncthreads();

    int cx = tid & 31;      // col quad (cols cx*4 .. cx*4+3)
    int ry = tid >> 5;      // warp id -> rows ry*4 .. ry*4+3
    float4 bv = *(const float4*)(bf + cx * 4);
    float4 a0 = bv, a1 = bv, a2 = bv, a3 = bv;

#pragma unroll
    for (int c = 0; c < 16; c++) {
        float4 wv = *(const float4*)(Wfs + c * 128 + cx * 4);
        float x0 = sx[(ry * 4 + 0) * 16 + c];
        float x1 = sx[(ry * 4 + 1) * 16 + c];
        float x2 = sx[(ry * 4 + 2) * 16 + c];
        float x3 = sx[(ry * 4 + 3) * 16 + c];
        a0.x = fmaf(x0, wv.x, a0.x); a0.y = fmaf(x0, wv.y, a0.y);
        a0.z = fmaf(x0, wv.z, a0.z); a0.w = fmaf(x0, wv.w, a0.w);
        a1.x = fmaf(x1, wv.x, a1.x); a1.y = fmaf(x1, wv.y, a1.y);
        a1.z = fmaf(x1, wv.z, a1.z); a1.w = fmaf(x1, wv.w, a1.w);
        a2.x = fmaf(x2, wv.x, a2.x); a2.y = fmaf(x2, wv.y, a2.y);
        a2.z = fmaf(x2, wv.z, a2.z); a2.w = fmaf(x2, wv.w, a2.w);
        a3.x = fmaf(x3, wv.x, a3.x); a3.y = fmaf(x3, wv.y, a3.y);
        a3.z = fmaf(x3, wv.z, a3.z); a3.w = fmaf(x3, wv.w, a3.w);
    }

    int u = u0 + ry * 4;
    if (u + 0 < U) *(float4*)(out + (u + 0) * 128 + cx * 4) = a0;
    if (u + 1 < U) *(float4*)(out + (u + 1) * 128 + cx * 4) = a1;
    if (u + 2 < U) *(float4*)(out + (u + 2) * 128 + cx * 4) = a2;
    if (u + 3 < U) *(float4*)(out + (u + 3) * 128 + cx * 4) = a3;
}

extern "C" void kernel_launch(void* const* d_in, const int* in_sizes, int n_in,
                              void* d_out, int out_size)
{
    const float* vox  = (const float*)d_in[0];
    const float* f2   = (const float*)d_in[1];
    const float* W0   = (const float*)d_in[2];
    const float* g0   = (const float*)d_in[3];
    const float* b0   = (const float*)d_in[4];
    const float* W1   = (const float*)d_in[5];
    const float* g1   = (const float*)d_in[6];
    const float* b1   = (const float*)d_in[7];
    const float* Wobo = (const float*)d_in[8];
    const float* bobo = (const float*)d_in[9];
    const float* Wf   = (const float*)d_in[10];
    const float* bf   = (const float*)d_in[11];
    const int*   nbr  = (const int*)d_in[12];
    const int*   seg  = (const int*)d_in[13];

    int N = in_sizes[0] / 16;
    int U = out_size / 128;

    void *p_merged, *p_y0, *p_y1;
    cudaGetSymbolAddress(&p_merged, g_merged);
    cudaGetSymbolAddress(&p_y0,     g_y0);
    cudaGetSymbolAddress(&p_y1,     g_y1);

    size_t mbytes = (size_t)U * 16 * sizeof(float);
    size_t mhalf  = (mbytes / 2) & ~(size_t)255;
    float invN = 1.0f / (float)N;
    int cblocks = (N + 127) / 128;

    // launch indices (ncu -s 5 -c 1 profiles index 5 = conv1)
    cudaMemsetAsync(p_merged, 0, mhalf);                                      // 0
    cudaMemsetAsync((char*)p_merged + mhalf, 0, mbytes - mhalf);              // 1
    zero_stats_kernel<<<1, 64>>>();                                           // 2
    fuse_t2_kernel<<<(N + 15) / 16, 256>>>(f2, Wobo, bobo, seg + N, N);       // 3
    conv_kernel<0><<<cblocks, 256>>>(vox, nbr, W0, (float*)p_y0,
                                     g0, b0, N, invN);                        // 4
    conv_kernel<1><<<cblocks, 256>>>((const float*)p_y0, nbr, W1,
                                     (float*)p_y1, g1, b1, N, invN);          // 5 (profiled)
    fuse_h_kernel<<<(N + 15) / 16, 256>>>((const float*)p_y1, g1, b1,
                                          seg, N, invN);                      // 6
    out_kernel<<<(U + 31) / 32, 256>>>(Wf, bf, (float*)d_out, U);             // 7
}

// round 8
// speedup vs baseline: 1.1796x; 1.1796x over previous
#include <cuda_runtime.h>

#define CEPS 1e-3f

// scratch (allocation-free rule: __device__ globals)
__device__ float g_y0[100000 * 16];
__device__ float g_y0b[100000 * 16];
__device__ float g_y1[100000 * 16];
__device__ float g_merged[200000 * 16];
__device__ float g_stats[64];   // [0:16) sum0, [16:32) sq0, [32:48) sum1, [48:64) sq1
__device__ int   g_nbrT[27 * 100000];

// ---------------------------------------------------------------------------
// Transpose rulebook: nbrT[k*N+n] = nbr[n*27+k]. Block: 256 rows.
// ---------------------------------------------------------------------------
__global__ __launch_bounds__(256) void transpose_nbr_kernel(
    const int* __restrict__ nbr, int N)
{
    __shared__ int t[256 * 27];
    int tid = threadIdx.x;
    int n0 = blockIdx.x * 256;
    int lim = (N - n0) * 27;
    for (int i = tid; i < 256 * 27; i += 256)
        t[i] = (i < lim) ? nbr[n0 * 27 + i] : -1;
    __syncthreads();
    int n = n0 + tid;
    if (n < N) {
#pragma unroll
        for (int k = 0; k < 27; k++)
            g_nbrT[k * N + n] = t[tid * 27 + k];
    }
}

// ---------------------------------------------------------------------------
// Submanifold 3x3x3 conv, register-direct gather.
// Thread = one row n, all 16 couts. Per k: coalesced nbrT load, 4x LDG.128
// gather into regs, broadcast-LDS W, 256 FMA. No staging, no inner barriers.
// Warp-uniform skip of k-offsets with no valid neighbors in the warp.
// ---------------------------------------------------------------------------
__global__ __launch_bounds__(256) void conv_kernel(
    const float* __restrict__ x, const float* __restrict__ W,
    float* __restrict__ y, int N, int statbase)
{
    __shared__ float Ws[27 * 256];   // 27.6 KB [k][c][o]
    __shared__ float sstat[32];

    int tid = threadIdx.x;
    for (int i = tid; i < 27 * 256; i += 256) Ws[i] = W[i];
    if (tid < 32) sstat[tid] = 0.f;
    __syncthreads();

    int n = blockIdx.x * 256 + tid;

    float4 a0 = make_float4(0.f, 0.f, 0.f, 0.f);
    float4 a1 = a0, a2 = a0, a3 = a0;

#define CSTEP(xc, cidx) {                                          \
        const float4* wp = (const float4*)(Wk + (cidx) * 16);      \
        float4 w0 = wp[0], w1 = wp[1], w2 = wp[2], w3 = wp[3];     \
        a0.x = fmaf(xc, w0.x, a0.x); a0.y = fmaf(xc, w0.y, a0.y);  \
        a0.z = fmaf(xc, w0.z, a0.z); a0.w = fmaf(xc, w0.w, a0.w);  \
        a1.x = fmaf(xc, w1.x, a1.x); a1.y = fmaf(xc, w1.y, a1.y);  \
        a1.z = fmaf(xc, w1.z, a1.z); a1.w = fmaf(xc, w1.w, a1.w);  \
        a2.x = fmaf(xc, w2.x, a2.x); a2.y = fmaf(xc, w2.y, a2.y);  \
        a2.z = fmaf(xc, w2.z, a2.z); a2.w = fmaf(xc, w2.w, a2.w);  \
        a3.x = fmaf(xc, w3.x, a3.x); a3.y = fmaf(xc, w3.y, a3.y);  \
        a3.z = fmaf(xc, w3.z, a3.z); a3.w = fmaf(xc, w3.w, a3.w);  }

    for (int k = 0; k < 27; k++) {
        int id = (n < N) ? g_nbrT[k * N + n] : -1;
        if (!__any_sync(0xffffffffu, id >= 0)) continue;

        float4 v0, v1, v2, v3;
        if (id >= 0) {
            const float4* xp = (const float4*)(x + id * 16);
            v0 = xp[0]; v1 = xp[1]; v2 = xp[2]; v3 = xp[3];
        } else {
            v0 = v1 = v2 = v3 = make_float4(0.f, 0.f, 0.f, 0.f);
        }
        const float* Wk = Ws + k * 256;
        CSTEP(v0.x, 0)  CSTEP(v0.y, 1)  CSTEP(v0.z, 2)  CSTEP(v0.w, 3)
        CSTEP(v1.x, 4)  CSTEP(v1.y, 5)  CSTEP(v1.z, 6)  CSTEP(v1.w, 7)
        CSTEP(v2.x, 8)  CSTEP(v2.y, 9)  CSTEP(v2.z, 10) CSTEP(v2.w, 11)
        CSTEP(v3.x, 12) CSTEP(v3.y, 13) CSTEP(v3.z, 14) CSTEP(v3.w, 15)
    }
#undef CSTEP

    if (n < N) {
        float4* yp = (float4*)(y + n * 16);
        yp[0] = a0; yp[1] = a1; yp[2] = a2; yp[3] = a3;
    }

    // ---- BN stats: per-channel butterfly, lane0 -> SMEM, block -> global ----
    float av[16] = {a0.x, a0.y, a0.z, a0.w, a1.x, a1.y, a1.z, a1.w,
                    a2.x, a2.y, a2.z, a2.w, a3.x, a3.y, a3.z, a3.w};
#pragma unroll
    for (int c = 0; c < 16; c++) {
        float s = av[c];
        float q = s * s;
#pragma unroll
        for (int off = 1; off < 32; off <<= 1) {
            s += __shfl_xor_sync(0xffffffffu, s, off);
            q += __shfl_xor_sync(0xffffffffu, q, off);
        }
        if ((tid & 31) == 0) {
            atomicAdd(&sstat[c], s);
            atomicAdd(&sstat[16 + c], q);
        }
    }
    __syncthreads();
    if (tid < 32) atomicAdd(&g_stats[statbase + tid], sstat[tid]);
}

// y0b = relu(bn0(y0)) elementwise (affine from g_stats base 0)
__global__ __launch_bounds__(256) void bnrelu_kernel(
    const float* __restrict__ yin, float* __restrict__ yout,
    const float* __restrict__ g, const float* __restrict__ b,
    int N, float invN)
{
    __shared__ float saff[32];
    int tid = threadIdx.x;
    if (tid < 16) {
        float mu  = g_stats[tid] * invN;
        float var = g_stats[16 + tid] * invN - mu * mu;
        float s   = g[tid] * rsqrtf(var + CEPS);
        saff[tid]      = s;
        saff[16 + tid] = b[tid] - mu * s;
    }
    __syncthreads();
    int i = blockIdx.x * 256 + tid;      // one float4 (4 channels) per thread
    if (i >= N * 4) return;
    int c4 = (i & 3) * 4;
    float4 v = *(const float4*)(yin + i * 4);
    v.x = fmaxf(fmaf(v.x, saff[c4 + 0], saff[16 + c4 + 0]), 0.f);
    v.y = fmaxf(fmaf(v.y, saff[c4 + 1], saff[16 + c4 + 1]), 0.f);
    v.z = fmaxf(fmaf(v.z, saff[c4 + 2], saff[16 + c4 + 2]), 0.f);
    v.w = fmaxf(fmaf(v.w, saff[c4 + 3], saff[16 + c4 + 3]), 0.f);
    *(float4*)(yout + i * 4) = v;
}

// tiny stats-zero kernel
__global__ void zero_stats_kernel() {
    if (threadIdx.x < 64) g_stats[threadIdx.x] = 0.f;
}

// t2 = f2 @ Wobo + bobo, atomicAdd-scatter into merged
__global__ __launch_bounds__(256) void fuse_t2_kernel(
    const float* __restrict__ f2, const float* __restrict__ Wobo,
    const float* __restrict__ bobo, const int* __restrict__ seg2, int N)
{
    __shared__ float Wo[256];
    __shared__ float sf[16 * 17];
    __shared__ float sb[16];
    int tid = threadIdx.x;
    Wo[tid] = Wobo[tid];
    if (tid < 16) sb[tid] = bobo[tid];
    int n0 = blockIdx.x * 16;
    if (tid < 64) {
        int r = tid >> 2, c4 = (tid & 3) * 4;
        float4 v = make_float4(0.f, 0.f, 0.f, 0.f);
        if (n0 + r < N) v = *(const float4*)(f2 + (n0 + r) * 16 + c4);
        sf[r * 17 + c4 + 0] = v.x; sf[r * 17 + c4 + 1] = v.y;
        sf[r * 17 + c4 + 2] = v.z; sf[r * 17 + c4 + 3] = v.w;
    }
    __syncthreads();
    int tx = tid & 15, ty = tid >> 4;
    int n = n0 + ty;
    if (n >= N) return;
    float acc = sb[tx];
#pragma unroll
    for (int c = 0; c < 16; c++)
        acc = fmaf(sf[ty * 17 + c], Wo[c * 16 + tx], acc);
    atomicAdd(&g_merged[seg2[n] * 16 + tx], acc);
}

// h = relu(bn1(y1)), atomicAdd-scatter into merged
__global__ __launch_bounds__(256) void fuse_h_kernel(
    const float* __restrict__ y1, const float* __restrict__ g1,
    const float* __restrict__ b1, const int* __restrict__ seg, int N, float invN)
{
    __shared__ float saff[32];
    int tid = threadIdx.x;
    if (tid < 16) {
        float mu  = g_stats[32 + tid] * invN;
        float var = g_stats[48 + tid] * invN - mu * mu;
        float s   = g1[tid] * rsqrtf(var + CEPS);
        saff[tid]      = s;
        saff[16 + tid] = b1[tid] - mu * s;
    }
    __syncthreads();
    int tx = tid & 15, ty = tid >> 4;
    int n = blockIdx.x * 16 + ty;
    if (n >= N) return;
    float h = fmaxf(fmaf(y1[n * 16 + tx], saff[tx], saff[16 + tx]), 0.f);
    atomicAdd(&g_merged[seg[n] * 16 + tx], h);
}

// out[u,:] = merged[u,:] @ Wf + bf.  32 rows x 128 cols per block.
__global__ __launch_bounds__(256) void out_kernel(
    const float* __restrict__ Wf, const float* __restrict__ bf,
    float* __restrict__ out, int U)
{
    __shared__ float Wfs[2048];
    __shared__ float sx[32 * 16];
    int tid = threadIdx.x;
    for (int i = tid; i < 2048; i += 256) Wfs[i] = Wf[i];
    int u0 = blockIdx.x * 32;
    if (tid < 128) {
        int r = tid >> 2, c4 = (tid & 3) * 4;
        float4 v = make_float4(0.f, 0.f, 0.f, 0.f);
        if (u0 + r < U) v = *(const float4*)(g_merged + (u0 + r) * 16 + c4);
        *(float4*)(sx + r * 16 + c4) = v;
    }
    __syncthreads();

    int cx = tid & 31, ry = tid >> 5;
    float4 bv = *(const float4*)(bf + cx * 4);
    float4 a0 = bv, a1 = bv, a2 = bv, a3 = bv;

#pragma unroll
    for (int c = 0; c < 16; c++) {
        float4 wv = *(const float4*)(Wfs + c * 128 + cx * 4);
        float x0 = sx[(ry * 4 + 0) * 16 + c];
        float x1 = sx[(ry * 4 + 1) * 16 + c];
        float x2 = sx[(ry * 4 + 2) * 16 + c];
        float x3 = sx[(ry * 4 + 3) * 16 + c];
        a0.x = fmaf(x0, wv.x, a0.x); a0.y = fmaf(x0, wv.y, a0.y);
        a0.z = fmaf(x0, wv.z, a0.z); a0.w = fmaf(x0, wv.w, a0.w);
        a1.x = fmaf(x1, wv.x, a1.x); a1.y = fmaf(x1, wv.y, a1.y);
        a1.z = fmaf(x1, wv.z, a1.z); a1.w = fmaf(x1, wv.w, a1.w);
        a2.x = fmaf(x2, wv.x, a2.x); a2.y = fmaf(x2, wv.y, a2.y);
        a2.z = fmaf(x2, wv.z, a2.z); a2.w = fmaf(x2, wv.w, a2.w);
        a3.x = fmaf(x3, wv.x, a3.x); a3.y = fmaf(x3, wv.y, a3.y);
        a3.z = fmaf(x3, wv.z, a3.z); a3.w = fmaf(x3, wv.w, a3.w);
    }

    int u = u0 + ry * 4;
    if (u + 0 < U) *(float4*)(out + (u + 0) * 128 + cx * 4) = a0;
    if (u + 1 < U) *(float4*)(out + (u + 1) * 128 + cx * 4) = a1;
    if (u + 2 < U) *(float4*)(out + (u + 2) * 128 + cx * 4) = a2;
    if (u + 3 < U) *(float4*)(out + (u + 3) * 128 + cx * 4) = a3;
}

extern "C" void kernel_launch(void* const* d_in, const int* in_sizes, int n_in,
                              void* d_out, int out_size)
{
    const float* vox  = (const float*)d_in[0];
    const float* f2   = (const float*)d_in[1];
    const float* W0   = (const float*)d_in[2];
    const float* g0   = (const float*)d_in[3];
    const float* b0   = (const float*)d_in[4];
    const float* W1   = (const float*)d_in[5];
    const float* g1   = (const float*)d_in[6];
    const float* b1   = (const float*)d_in[7];
    const float* Wobo = (const float*)d_in[8];
    const float* bobo = (const float*)d_in[9];
    const float* Wf   = (const float*)d_in[10];
    const float* bf   = (const float*)d_in[11];
    const int*   nbr  = (const int*)d_in[12];
    const int*   seg  = (const int*)d_in[13];

    int N = in_sizes[0] / 16;
    int U = out_size / 128;

    void *p_merged, *p_y0, *p_y0b, *p_y1;
    cudaGetSymbolAddress(&p_merged, g_merged);
    cudaGetSymbolAddress(&p_y0,     g_y0);
    cudaGetSymbolAddress(&p_y0b,    g_y0b);
    cudaGetSymbolAddress(&p_y1,     g_y1);

    size_t mbytes = (size_t)U * 16 * sizeof(float);
    size_t mhalf  = (mbytes / 2) & ~(size_t)255;
    float invN = 1.0f / (float)N;
    int cblocks = (N + 255) / 256;

    // launch indices (ncu -s 5 -c 1 profiles index 5 = conv0)
    cudaMemsetAsync(p_merged, 0, mhalf);                                      // 0
    cudaMemsetAsync((char*)p_merged + mhalf, 0, mbytes - mhalf);              // 1
    zero_stats_kernel<<<1, 64>>>();                                           // 2
    transpose_nbr_kernel<<<cblocks, 256>>>(nbr, N);                           // 3
    fuse_t2_kernel<<<(N + 15) / 16, 256>>>(f2, Wobo, bobo, seg + N, N);       // 4
    conv_kernel<<<cblocks, 256>>>(vox, W0, (float*)p_y0, N, 0);               // 5 (profiled)
    bnrelu_kernel<<<(N * 4 + 255) / 256, 256>>>((const float*)p_y0,
                                                (float*)p_y0b, g0, b0,
                                                N, invN);                     // 6
    conv_kernel<<<cblocks, 256>>>((const float*)p_y0b, W1,
                                  (float*)p_y1, N, 32);                       // 7
    fuse_h_kernel<<<(N + 15) / 16, 256>>>((const float*)p_y1, g1, b1,
                                          seg, N, invN);                      // 8
    out_kernel<<<(U + 31) / 32, 256>>>(Wf, bf, (float*)d_out, U);             // 9
}